// round 11
// baseline (speedup 1.0000x reference)
#include <cuda_runtime.h>
#include <cuda_fp16.h>
#include <cstdint>

// ---------------------------------------------------------------------------
// Problem constants
// ---------------------------------------------------------------------------
#define N_IMG   16
#define C_IN    64
#define C_OUT   64
#define HH      128
#define WW      128
#define W_ELEMS (C_OUT * C_IN * 9)      // 36864
#define HP      130                      // padded H/W
#define XP_ELEMS (N_IMG * HP * HP * 64)  // fp16 padded NHWC scratch

// ---------------------------------------------------------------------------
// Persistent device scratch (zero-initialized; g_xp borders stay 0 forever)
// ---------------------------------------------------------------------------
__device__ double  g_part[32];
__device__ __half  g_xp[XP_ELEMS];        // [n][h+1][w+1][c]
__device__ __half  g_wB[9 * 64 * 64];     // [tap][oc][c]
__device__ float   g_beff[C_OUT];

// ---------------------------------------------------------------------------
// PTX helpers (sm_103-baseline: cp.async, ldmatrix, mma.sync)
// ---------------------------------------------------------------------------
__device__ __forceinline__ uint32_t smem_to_u32(const void* p) {
    uint32_t a;
    asm("{ .reg .u64 t; cvta.to.shared.u64 t, %1; cvt.u32.u64 %0, t; }"
        : "=r"(a) : "l"(p));
    return a;
}
__device__ __forceinline__ void cp16(uint32_t dst, const void* src) {
    asm volatile("cp.async.cg.shared.global [%0], [%1], 16;" :: "r"(dst), "l"(src));
}
__device__ __forceinline__ void cp_commit() {
    asm volatile("cp.async.commit_group;" ::: "memory");
}
__device__ __forceinline__ void cp_wait0() {
    asm volatile("cp.async.wait_group 0;" ::: "memory");
}
__device__ __forceinline__ void cp_wait1() {
    asm volatile("cp.async.wait_group 1;" ::: "memory");
}
__device__ __forceinline__ void ldsm_x4(uint32_t* r, uint32_t addr) {
    asm volatile("ldmatrix.sync.aligned.m8n8.x4.shared.b16 {%0,%1,%2,%3}, [%4];"
        : "=r"(r[0]), "=r"(r[1]), "=r"(r[2]), "=r"(r[3]) : "r"(addr));
}
__device__ __forceinline__ void mma16816(float* d, const uint32_t* a, const uint32_t* b) {
    asm volatile(
        "mma.sync.aligned.m16n8k16.row.col.f32.f16.f16.f32 "
        "{%0,%1,%2,%3}, {%4,%5,%6,%7}, {%8,%9}, {%0,%1,%2,%3};"
        : "+f"(d[0]), "+f"(d[1]), "+f"(d[2]), "+f"(d[3])
        : "r"(a[0]), "r"(a[1]), "r"(a[2]), "r"(a[3]), "r"(b[0]), "r"(b[1]));
}

// ---------------------------------------------------------------------------
// Kernel 1: fused  (blocks 0..31: fp64 |w| partial sums)
//   (blocks 32..: NCHW fp32 -> padded NHWC fp16 transpose, TWO h-rows/block,
//    4 independent LDG.128 per thread in flight before the sync — MLP=4)
// ---------------------------------------------------------------------------
__global__ __launch_bounds__(256)
void transpose_scale_kernel(const float* __restrict__ x,
                            const float* __restrict__ w,
                            const float* __restrict__ wc) {
    const int tid = threadIdx.x;
    if (blockIdx.x < 32) {
        int b = blockIdx.x;
        const float* p = (b < 16) ? w : wc;
        int seg = b & 15;
        int start = seg * (W_ELEMS / 16);
        double s = 0.0;
        for (int i = start + tid; i < start + W_ELEMS / 16; i += 256)
            s += (double)fabsf(p[i]);
        __shared__ double red[256];
        red[tid] = s;
        __syncthreads();
        for (int off = 128; off > 0; off >>= 1) {
            if (tid < off) red[tid] += red[tid + off];
            __syncthreads();
        }
        if (tid == 0) g_part[b] = red[0];
        return;
    }

    const int idx = blockIdx.x - 32;          // 0..4095
    const int w0 = (idx & 3) * 32;
    const int h0 = ((idx >> 2) & 63) * 2;     // two rows per block
    const int n  = idx >> 8;

    __shared__ float s[2][32 * 65];

    // 4 independent LDG.128 per thread: 2 chunk-slots x 2 rows.
    // Slots i = tid, tid+256 cover all 64 channels x 8 chunks (512 slots).
    float4 v[2][2];
    int cc[2], jj[2];
#pragma unroll
    for (int it = 0; it < 2; ++it) {
        int i = tid + it * 256;
        cc[it] = i >> 3;                      // channel 0..63
        jj[it] = i & 7;                       // 16B chunk within row
#pragma unroll
        for (int r = 0; r < 2; ++r)
            v[it][r] = *reinterpret_cast<const float4*>(
                x + (((size_t)(n * 64 + cc[it])) * HH + (h0 + r)) * WW
                  + w0 + jj[it] * 4);
    }
#pragma unroll
    for (int it = 0; it < 2; ++it) {
        int wb = jj[it] * 4, c = cc[it];
#pragma unroll
        for (int r = 0; r < 2; ++r) {
            s[r][(wb + 0) * 65 + c] = v[it][r].x;
            s[r][(wb + 1) * 65 + c] = v[it][r].y;
            s[r][(wb + 2) * 65 + c] = v[it][r].z;
            s[r][(wb + 3) * 65 + c] = v[it][r].w;
        }
    }
    __syncthreads();

    const int wcx = tid >> 3;                 // pixel within 32
    const int cg  = (tid & 7) * 8;            // channel group of 8
#pragma unroll
    for (int r = 0; r < 2; ++r) {
        alignas(16) __half h8[8];
#pragma unroll
        for (int k = 0; k < 8; ++k)
            h8[k] = __float2half_rn(s[r][wcx * 65 + cg + k]);
        size_t dst = (((size_t)n * HP + (h0 + r + 1)) * HP + (w0 + wcx + 1)) * 64 + cg;
        *reinterpret_cast<uint4*>(&g_xp[dst]) = *reinterpret_cast<const uint4*>(h8);
    }
}

// ---------------------------------------------------------------------------
// Kernel 2: finalize scales (redundant per block) + fuse ternary weights
// ---------------------------------------------------------------------------
__global__ void prep_kernel(const float* __restrict__ w,
                            const float* __restrict__ b,
                            const float* __restrict__ wc,
                            const float* __restrict__ bc,
                            const float* __restrict__ gate) {
    __shared__ float ssc[2];
    if (threadIdx.x < 2) {
        double s = 0.0;
        for (int i = 0; i < 16; ++i) s += g_part[threadIdx.x * 16 + i];
        ssc[threadIdx.x] = fmaxf((float)(s / (double)W_ELEMS), 1e-5f);
    }
    __syncthreads();
    int i = blockIdx.x * 256 + threadIdx.x;
    float g = 1.0f / (1.0f + expf(-gate[0]));
    if (i < W_ELEMS) {
        float s1 = ssc[0], s2 = ssc[1];
        float q1 = fminf(fmaxf(rintf(w[i]  / s1), -1.0f), 1.0f) * s1;
        float q2 = fminf(fmaxf(rintf(wc[i] / s2), -1.0f), 1.0f) * s2;
        int o = i / (C_IN * 9);
        int r = i - o * (C_IN * 9);
        int c = r / 9;
        int k = r - c * 9;
        g_wB[k * 4096 + o * 64 + c] = __float2half_rn(q1 + g * q2);
    }
    if (i < C_OUT)
        g_beff[i] = b[i] + g * bc[i];
}

// ---------------------------------------------------------------------------
// Kernel 3: persistent implicit-GEMM conv via HMMA (ROUND-4 PROVEN CONFIG:
//   256 threads, warp tile m32n64, tile = 2 output rows M=256 x N=64,
//   whole-tile double buffer, 148 persistent CTAs, full dx/kc unroll)
// SMEM: B [0,73728) | A 2 x 4rows [73728, 206848)
// ---------------------------------------------------------------------------
#define AROW_B   16640              // 130*128
#define ABUF_B   (4 * AROW_B)       // 66560
#define A_OFF    73728
#define SMEM_CONV 206848
#define NTILES2  1024               // 16 images * 64 row-pairs

__device__ __forceinline__ void stage_A(uint32_t abuf, int t, int tid) {
    const int n = t >> 6, y0 = (t & 63) * 2;
    const char* src = reinterpret_cast<const char*>(
        g_xp + ((size_t)n * HP + y0) * HP * 64);
    for (int i = tid; i < 4160; i += 256) {       // 4 rows x 1040 16B-chunks
        int r = i / 1040;
        int k = i - r * 1040;
        int p = k >> 3, j = k & 7;
        cp16(abuf + r * AROW_B + p * 128 + ((j ^ (p & 7)) << 4),
             src + (size_t)r * AROW_B + (size_t)k * 16);
    }
}

__global__ __launch_bounds__(256, 1)
void conv_kernel(float* __restrict__ out) {
    extern __shared__ char sm[];
    const uint32_t base = smem_to_u32(sm);
    const int tid  = threadIdx.x;
    const int wid  = tid >> 5;
    const int lane = tid & 31;

    // Stage all 9 weight tiles (swizzle: chunk j of oc-row nr -> j^(nr&7))
    for (int k = tid; k < 4608; k += 256) {
        int q = k & 511;
        int nr = q >> 3, j = q & 7;
        cp16(base + (k >> 9) * 8192 + nr * 128 + ((j ^ (nr & 7)) << 4),
             reinterpret_cast<const char*>(g_wB) + (size_t)k * 16);
    }
    cp_commit();

    const int t0 = blockIdx.x;
    if (t0 < NTILES2) stage_A(base + A_OFF, t0, tid);
    cp_commit();
    cp_wait0();
    __syncthreads();

    // Warp layout: rw = output row within pair, m0 = 32-pixel quadrant
    const int rw = wid >> 2;
    const int m0 = (wid & 3) * 32;
    const int a_pl = lane & 15, a_hk = lane >> 4;
    const int b_nl = (lane & 7) + ((lane >> 4) << 3);
    const int b_hk = (lane >> 3) & 1;

    // Per-thread bias registers: oc = nj*8 + (lane&3)*2 + {0,1}
    float bv[8][2];
#pragma unroll
    for (int nj = 0; nj < 8; ++nj) {
        bv[nj][0] = g_beff[nj * 8 + (lane & 3) * 2];
        bv[nj][1] = g_beff[nj * 8 + (lane & 3) * 2 + 1];
    }

    int buf = 0;
    for (int t = t0; t < NTILES2; t += gridDim.x) {
        const int nxt = t + gridDim.x;
        if (nxt < NTILES2) {
            stage_A(base + A_OFF + (buf ^ 1) * ABUF_B, nxt, tid);
            cp_commit();
        }
        if (t != t0) {
            if (nxt < NTILES2) cp_wait1(); else cp_wait0();
            __syncthreads();
        }

        float acc[2][8][4];
#pragma unroll
        for (int mi = 0; mi < 2; ++mi)
#pragma unroll
            for (int nj = 0; nj < 8; ++nj)
#pragma unroll
                for (int r = 0; r < 4; ++r) acc[mi][nj][r] = 0.0f;

        const uint32_t abase = base + A_OFF + buf * ABUF_B;
#pragma unroll 1
        for (int dy = 0; dy < 3; ++dy) {
            const uint32_t arow = abase + (rw + dy) * AROW_B;
#pragma unroll
            for (int dx = 0; dx < 3; ++dx) {
                const uint32_t btap = base + (dy * 3 + dx) * 8192;
#pragma unroll
                for (int kc = 0; kc < 4; ++kc) {
                    uint32_t a[2][4];
#pragma unroll
                    for (int mi = 0; mi < 2; ++mi) {
                        int pix = m0 + mi * 16 + a_pl + dx;
                        ldsm_x4(a[mi], arow + pix * 128 +
                                (((2 * kc + a_hk) ^ (pix & 7)) << 4));
                    }
#pragma unroll
                    for (int nj = 0; nj < 4; ++nj) {
                        uint32_t b[4];
                        int nn = nj * 16 + b_nl;
                        ldsm_x4(b, btap + nn * 128 +
                                (((2 * kc + b_hk) ^ (b_nl & 7)) << 4));
#pragma unroll
                        for (int mi = 0; mi < 2; ++mi) {
                            mma16816(acc[mi][nj * 2 + 0], a[mi], b + 0);
                            mma16816(acc[mi][nj * 2 + 1], a[mi], b + 2);
                        }
                    }
                }
            }
        }

        // Direct epilogue: STG.32 from fragments, bias fused in registers
        {
            const int n = t >> 6, y = (t & 63) * 2 + rw;
            float* ob = out + (size_t)n * (64 * 16384) + (size_t)y * 128;
            const int pl = lane >> 2;
#pragma unroll
            for (int mi = 0; mi < 2; ++mi) {
                int pbase = m0 + mi * 16 + pl;
#pragma unroll
                for (int nj = 0; nj < 8; ++nj) {
                    float* p0 = ob + (size_t)(nj * 8 + (lane & 3) * 2) * 16384;
                    p0[pbase]             = acc[mi][nj][0] + bv[nj][0];
                    p0[16384 + pbase]     = acc[mi][nj][1] + bv[nj][1];
                    p0[pbase + 8]         = acc[mi][nj][2] + bv[nj][0];
                    p0[16384 + pbase + 8] = acc[mi][nj][3] + bv[nj][1];
                }
            }
        }
        __syncthreads();   // all warps done reading buf before it is restaged
        buf ^= 1;
    }
}

// ---------------------------------------------------------------------------
extern "C" void kernel_launch(void* const* d_in, const int* in_sizes, int n_in,
                              void* d_out, int out_size) {
    const float* x  = (const float*)d_in[0];
    const float* w  = (const float*)d_in[1];
    const float* b  = (const float*)d_in[2];
    const float* wc = (const float*)d_in[3];
    const float* bc = (const float*)d_in[4];
    const float* gt = (const float*)d_in[5];
    float* out = (float*)d_out;

    static bool attr_set = false;
    if (!attr_set) {
        cudaFuncSetAttribute(conv_kernel,
                             cudaFuncAttributeMaxDynamicSharedMemorySize, SMEM_CONV);
        attr_set = true;
    }

    transpose_scale_kernel<<<4096 + 32, 256>>>(x, w, wc);
    prep_kernel<<<(W_ELEMS + 255) / 256, 256>>>(w, b, wc, bc, gt);
    conv_kernel<<<148, 256, SMEM_CONV>>>(out);
}

// round 12
// speedup vs baseline: 1.4335x; 1.4335x over previous
#include <cuda_runtime.h>
#include <cuda_fp16.h>
#include <cstdint>

// ---------------------------------------------------------------------------
// Problem constants
// ---------------------------------------------------------------------------
#define N_IMG   16
#define C_IN    64
#define C_OUT   64
#define HH      128
#define WW      128
#define W_ELEMS (C_OUT * C_IN * 9)      // 36864
#define HP      130                      // padded H/W
#define XP_ELEMS (N_IMG * HP * HP * 64)  // fp16 padded NHWC scratch

// ---------------------------------------------------------------------------
// Persistent device scratch (zero-initialized; g_xp borders stay 0 forever)
// ---------------------------------------------------------------------------
__device__ double  g_part[32];
__device__ __half  g_xp[XP_ELEMS];        // [n][h+1][w+1][c]
__device__ __half  g_wB[9 * 64 * 64];     // [tap][oc][c]
__device__ float   g_beff[C_OUT];

// ---------------------------------------------------------------------------
// PTX helpers (sm_103-baseline: cp.async, ldmatrix, mma.sync)
// ---------------------------------------------------------------------------
__device__ __forceinline__ uint32_t smem_to_u32(const void* p) {
    uint32_t a;
    asm("{ .reg .u64 t; cvta.to.shared.u64 t, %1; cvt.u32.u64 %0, t; }"
        : "=r"(a) : "l"(p));
    return a;
}
__device__ __forceinline__ void cp16(uint32_t dst, const void* src) {
    asm volatile("cp.async.cg.shared.global [%0], [%1], 16;" :: "r"(dst), "l"(src));
}
__device__ __forceinline__ void cp_commit() {
    asm volatile("cp.async.commit_group;" ::: "memory");
}
__device__ __forceinline__ void cp_wait0() {
    asm volatile("cp.async.wait_group 0;" ::: "memory");
}
__device__ __forceinline__ void cp_wait1() {
    asm volatile("cp.async.wait_group 1;" ::: "memory");
}
__device__ __forceinline__ void ldsm_x4(uint32_t* r, uint32_t addr) {
    asm volatile("ldmatrix.sync.aligned.m8n8.x4.shared.b16 {%0,%1,%2,%3}, [%4];"
        : "=r"(r[0]), "=r"(r[1]), "=r"(r[2]), "=r"(r[3]) : "r"(addr));
}
__device__ __forceinline__ void mma16816(float* d, const uint32_t* a, const uint32_t* b) {
    asm volatile(
        "mma.sync.aligned.m16n8k16.row.col.f32.f16.f16.f32 "
        "{%0,%1,%2,%3}, {%4,%5,%6,%7}, {%8,%9}, {%0,%1,%2,%3};"
        : "+f"(d[0]), "+f"(d[1]), "+f"(d[2]), "+f"(d[3])
        : "r"(a[0]), "r"(a[1]), "r"(a[2]), "r"(a[3]), "r"(b[0]), "r"(b[1]));
}

// ---------------------------------------------------------------------------
// Kernel 1: fused  (blocks 0..31: fp64 |w| partial sums)
//   (blocks 32..: NCHW fp32 -> padded NHWC fp16 transpose — PROVEN one-row
//    version: 2 independent LDG.128/thread, 18.1-18.6us across 4 runs)
// ---------------------------------------------------------------------------
__global__ __launch_bounds__(256)
void transpose_scale_kernel(const float* __restrict__ x,
                            const float* __restrict__ w,
                            const float* __restrict__ wc) {
    const int tid = threadIdx.x;
    if (blockIdx.x < 32) {
        int b = blockIdx.x;
        const float* p = (b < 16) ? w : wc;
        int seg = b & 15;
        int start = seg * (W_ELEMS / 16);
        double s = 0.0;
        for (int i = start + tid; i < start + W_ELEMS / 16; i += 256)
            s += (double)fabsf(p[i]);
        __shared__ double red[256];
        red[tid] = s;
        __syncthreads();
        for (int off = 128; off > 0; off >>= 1) {
            if (tid < off) red[tid] += red[tid + off];
            __syncthreads();
        }
        if (tid == 0) g_part[b] = red[0];
        return;
    }

    const int idx = blockIdx.x - 32;
    const int w0 = (idx & 3) * 32;
    const int h  = (idx >> 2) & 127;
    const int n  = idx >> 9;

    __shared__ float s[32 * 65];
#pragma unroll
    for (int it = 0; it < 2; ++it) {
        int i = tid + it * 256;            // 0..511 = 64ch x 8 chunks
        int c = i >> 3, j = i & 7;
        float4 v = *reinterpret_cast<const float4*>(
            x + (((size_t)(n * 64 + c)) * HH + h) * WW + w0 + j * 4);
        int wb = j * 4;
        s[(wb + 0) * 65 + c] = v.x;
        s[(wb + 1) * 65 + c] = v.y;
        s[(wb + 2) * 65 + c] = v.z;
        s[(wb + 3) * 65 + c] = v.w;
    }
    __syncthreads();

    int wcx = tid >> 3;
    int cg = (tid & 7) * 8;
    alignas(16) __half h8[8];
#pragma unroll
    for (int j = 0; j < 8; ++j)
        h8[j] = __float2half_rn(s[wcx * 65 + cg + j]);
    size_t dst = (((size_t)n * HP + (h + 1)) * HP + (w0 + wcx + 1)) * 64 + cg;
    *reinterpret_cast<uint4*>(&g_xp[dst]) = *reinterpret_cast<const uint4*>(h8);
}

// ---------------------------------------------------------------------------
// Kernel 2: finalize scales (redundant per block) + fuse ternary weights
// ---------------------------------------------------------------------------
__global__ void prep_kernel(const float* __restrict__ w,
                            const float* __restrict__ b,
                            const float* __restrict__ wc,
                            const float* __restrict__ bc,
                            const float* __restrict__ gate) {
    __shared__ float ssc[2];
    if (threadIdx.x < 2) {
        double s = 0.0;
        for (int i = 0; i < 16; ++i) s += g_part[threadIdx.x * 16 + i];
        ssc[threadIdx.x] = fmaxf((float)(s / (double)W_ELEMS), 1e-5f);
    }
    __syncthreads();
    int i = blockIdx.x * 256 + threadIdx.x;
    float g = 1.0f / (1.0f + expf(-gate[0]));
    if (i < W_ELEMS) {
        float s1 = ssc[0], s2 = ssc[1];
        float q1 = fminf(fmaxf(rintf(w[i]  / s1), -1.0f), 1.0f) * s1;
        float q2 = fminf(fmaxf(rintf(wc[i] / s2), -1.0f), 1.0f) * s2;
        int o = i / (C_IN * 9);
        int r = i - o * (C_IN * 9);
        int c = r / 9;
        int k = r - c * 9;
        g_wB[k * 4096 + o * 64 + c] = __float2half_rn(q1 + g * q2);
    }
    if (i < C_OUT)
        g_beff[i] = b[i] + g * bc[i];
}

// ---------------------------------------------------------------------------
// Kernel 3: persistent implicit-GEMM conv via HMMA (ROUND-4 PROVEN CONFIG,
//   single delta: dy loop now FULLY UNROLLED so ptxas can software-pipeline
//   LDSM->MMA across all 36 k-steps instead of draining at dy boundaries)
// SMEM: B [0,73728) | A 2 x 4rows [73728, 206848)
// ---------------------------------------------------------------------------
#define AROW_B   16640              // 130*128
#define ABUF_B   (4 * AROW_B)       // 66560
#define A_OFF    73728
#define SMEM_CONV 206848
#define NTILES2  1024               // 16 images * 64 row-pairs

__device__ __forceinline__ void stage_A(uint32_t abuf, int t, int tid) {
    const int n = t >> 6, y0 = (t & 63) * 2;
    const char* src = reinterpret_cast<const char*>(
        g_xp + ((size_t)n * HP + y0) * HP * 64);
    for (int i = tid; i < 4160; i += 256) {       // 4 rows x 1040 16B-chunks
        int r = i / 1040;
        int k = i - r * 1040;
        int p = k >> 3, j = k & 7;
        cp16(abuf + r * AROW_B + p * 128 + ((j ^ (p & 7)) << 4),
             src + (size_t)r * AROW_B + (size_t)k * 16);
    }
}

__global__ __launch_bounds__(256, 1)
void conv_kernel(float* __restrict__ out) {
    extern __shared__ char sm[];
    const uint32_t base = smem_to_u32(sm);
    const int tid  = threadIdx.x;
    const int wid  = tid >> 5;
    const int lane = tid & 31;

    // Stage all 9 weight tiles (swizzle: chunk j of oc-row nr -> j^(nr&7))
    for (int k = tid; k < 4608; k += 256) {
        int q = k & 511;
        int nr = q >> 3, j = q & 7;
        cp16(base + (k >> 9) * 8192 + nr * 128 + ((j ^ (nr & 7)) << 4),
             reinterpret_cast<const char*>(g_wB) + (size_t)k * 16);
    }
    cp_commit();

    const int t0 = blockIdx.x;
    if (t0 < NTILES2) stage_A(base + A_OFF, t0, tid);
    cp_commit();
    cp_wait0();
    __syncthreads();

    // Warp layout: rw = output row within pair, m0 = 32-pixel quadrant
    const int rw = wid >> 2;
    const int m0 = (wid & 3) * 32;
    const int a_pl = lane & 15, a_hk = lane >> 4;
    const int b_nl = (lane & 7) + ((lane >> 4) << 3);
    const int b_hk = (lane >> 3) & 1;

    // Per-thread bias registers: oc = nj*8 + (lane&3)*2 + {0,1}
    float bv[8][2];
#pragma unroll
    for (int nj = 0; nj < 8; ++nj) {
        bv[nj][0] = g_beff[nj * 8 + (lane & 3) * 2];
        bv[nj][1] = g_beff[nj * 8 + (lane & 3) * 2 + 1];
    }

    int buf = 0;
    for (int t = t0; t < NTILES2; t += gridDim.x) {
        const int nxt = t + gridDim.x;
        if (nxt < NTILES2) {
            stage_A(base + A_OFF + (buf ^ 1) * ABUF_B, nxt, tid);
            cp_commit();
        }
        if (t != t0) {
            if (nxt < NTILES2) cp_wait1(); else cp_wait0();
            __syncthreads();
        }

        float acc[2][8][4];
#pragma unroll
        for (int mi = 0; mi < 2; ++mi)
#pragma unroll
            for (int nj = 0; nj < 8; ++nj)
#pragma unroll
                for (int r = 0; r < 4; ++r) acc[mi][nj][r] = 0.0f;

        const uint32_t abase = base + A_OFF + buf * ABUF_B;
#pragma unroll
        for (int dy = 0; dy < 3; ++dy) {          // <-- full unroll (the delta)
            const uint32_t arow = abase + (rw + dy) * AROW_B;
#pragma unroll
            for (int dx = 0; dx < 3; ++dx) {
                const uint32_t btap = base + (dy * 3 + dx) * 8192;
#pragma unroll
                for (int kc = 0; kc < 4; ++kc) {
                    uint32_t a[2][4];
#pragma unroll
                    for (int mi = 0; mi < 2; ++mi) {
                        int pix = m0 + mi * 16 + a_pl + dx;
                        ldsm_x4(a[mi], arow + pix * 128 +
                                (((2 * kc + a_hk) ^ (pix & 7)) << 4));
                    }
#pragma unroll
                    for (int nj = 0; nj < 4; ++nj) {
                        uint32_t b[4];
                        int nn = nj * 16 + b_nl;
                        ldsm_x4(b, btap + nn * 128 +
                                (((2 * kc + b_hk) ^ (b_nl & 7)) << 4));
#pragma unroll
                        for (int mi = 0; mi < 2; ++mi) {
                            mma16816(acc[mi][nj * 2 + 0], a[mi], b + 0);
                            mma16816(acc[mi][nj * 2 + 1], a[mi], b + 2);
                        }
                    }
                }
            }
        }

        // Direct epilogue: STG.32 from fragments, bias fused in registers
        {
            const int n = t >> 6, y = (t & 63) * 2 + rw;
            float* ob = out + (size_t)n * (64 * 16384) + (size_t)y * 128;
            const int pl = lane >> 2;
#pragma unroll
            for (int mi = 0; mi < 2; ++mi) {
                int pbase = m0 + mi * 16 + pl;
#pragma unroll
                for (int nj = 0; nj < 8; ++nj) {
                    float* p0 = ob + (size_t)(nj * 8 + (lane & 3) * 2) * 16384;
                    p0[pbase]             = acc[mi][nj][0] + bv[nj][0];
                    p0[16384 + pbase]     = acc[mi][nj][1] + bv[nj][1];
                    p0[pbase + 8]         = acc[mi][nj][2] + bv[nj][0];
                    p0[16384 + pbase + 8] = acc[mi][nj][3] + bv[nj][1];
                }
            }
        }
        __syncthreads();   // all warps done reading buf before it is restaged
        buf ^= 1;
    }
}

// ---------------------------------------------------------------------------
extern "C" void kernel_launch(void* const* d_in, const int* in_sizes, int n_in,
                              void* d_out, int out_size) {
    const float* x  = (const float*)d_in[0];
    const float* w  = (const float*)d_in[1];
    const float* b  = (const float*)d_in[2];
    const float* wc = (const float*)d_in[3];
    const float* bc = (const float*)d_in[4];
    const float* gt = (const float*)d_in[5];
    float* out = (float*)d_out;

    static bool attr_set = false;
    if (!attr_set) {
        cudaFuncSetAttribute(conv_kernel,
                             cudaFuncAttributeMaxDynamicSharedMemorySize, SMEM_CONV);
        attr_set = true;
    }

    transpose_scale_kernel<<<8192 + 32, 256>>>(x, w, wc);
    prep_kernel<<<(W_ELEMS + 255) / 256, 256>>>(w, b, wc, bc, gt);
    conv_kernel<<<148, 256, SMEM_CONV>>>(out);
}

// round 13
// speedup vs baseline: 1.4737x; 1.0280x over previous
#include <cuda_runtime.h>
#include <cuda_fp16.h>
#include <cstdint>

// ---------------------------------------------------------------------------
// Problem constants
// ---------------------------------------------------------------------------
#define N_IMG   16
#define C_IN    64
#define C_OUT   64
#define HH      128
#define WW      128
#define W_ELEMS (C_OUT * C_IN * 9)      // 36864
#define HP      130                      // padded H/W
#define XP_ELEMS (N_IMG * HP * HP * 64)  // fp16 padded NHWC scratch

// ---------------------------------------------------------------------------
// Persistent device scratch (zero-initialized; g_xp borders stay 0 forever)
// ---------------------------------------------------------------------------
__device__ double  g_part[32];
__device__ __half  g_xp[XP_ELEMS];        // [n][h+1][w+1][c]
__device__ __half  g_wB[9 * 64 * 64];     // [tap][oc][c]
__device__ float   g_beff[C_OUT];

// ---------------------------------------------------------------------------
// PTX helpers (sm_103-baseline: cp.async, ldmatrix, mma.sync)
// ---------------------------------------------------------------------------
__device__ __forceinline__ uint32_t smem_to_u32(const void* p) {
    uint32_t a;
    asm("{ .reg .u64 t; cvta.to.shared.u64 t, %1; cvt.u32.u64 %0, t; }"
        : "=r"(a) : "l"(p));
    return a;
}
__device__ __forceinline__ void cp16(uint32_t dst, const void* src) {
    asm volatile("cp.async.cg.shared.global [%0], [%1], 16;" :: "r"(dst), "l"(src));
}
__device__ __forceinline__ void cp_commit() {
    asm volatile("cp.async.commit_group;" ::: "memory");
}
__device__ __forceinline__ void cp_wait0() {
    asm volatile("cp.async.wait_group 0;" ::: "memory");
}
__device__ __forceinline__ void ldsm_x4(uint32_t* r, uint32_t addr) {
    asm volatile("ldmatrix.sync.aligned.m8n8.x4.shared.b16 {%0,%1,%2,%3}, [%4];"
        : "=r"(r[0]), "=r"(r[1]), "=r"(r[2]), "=r"(r[3]) : "r"(addr));
}
__device__ __forceinline__ void mma16816(float* d, const uint32_t* a, const uint32_t* b) {
    asm volatile(
        "mma.sync.aligned.m16n8k16.row.col.f32.f16.f16.f32 "
        "{%0,%1,%2,%3}, {%4,%5,%6,%7}, {%8,%9}, {%0,%1,%2,%3};"
        : "+f"(d[0]), "+f"(d[1]), "+f"(d[2]), "+f"(d[3])
        : "r"(a[0]), "r"(a[1]), "r"(a[2]), "r"(a[3]), "r"(b[0]), "r"(b[1]));
}
// evict-first streaming load (x is single-use)
__device__ __forceinline__ float4 ldg_cs_f4(const float* p) {
    float4 v;
    asm volatile("ld.global.cs.v4.f32 {%0,%1,%2,%3}, [%4];"
        : "=f"(v.x), "=f"(v.y), "=f"(v.z), "=f"(v.w) : "l"(p));
    return v;
}

// ---------------------------------------------------------------------------
// Kernel 1: fused  (blocks 0..31: fp64 |w| partial sums)
//   (blocks 32..: NCHW fp32 -> padded NHWC fp16 transpose — PROVEN one-row
//    version, x loads now evict-first to keep g_xp resident in L2)
// ---------------------------------------------------------------------------
__global__ __launch_bounds__(256)
void transpose_scale_kernel(const float* __restrict__ x,
                            const float* __restrict__ w,
                            const float* __restrict__ wc) {
    const int tid = threadIdx.x;
    if (blockIdx.x < 32) {
        int b = blockIdx.x;
        const float* p = (b < 16) ? w : wc;
        int seg = b & 15;
        int start = seg * (W_ELEMS / 16);
        double s = 0.0;
        for (int i = start + tid; i < start + W_ELEMS / 16; i += 256)
            s += (double)fabsf(p[i]);
        __shared__ double red[256];
        red[tid] = s;
        __syncthreads();
        for (int off = 128; off > 0; off >>= 1) {
            if (tid < off) red[tid] += red[tid + off];
            __syncthreads();
        }
        if (tid == 0) g_part[b] = red[0];
        return;
    }

    const int idx = blockIdx.x - 32;
    const int w0 = (idx & 3) * 32;
    const int h  = (idx >> 2) & 127;
    const int n  = idx >> 9;

    __shared__ float s[32 * 65];
#pragma unroll
    for (int it = 0; it < 2; ++it) {
        int i = tid + it * 256;            // 0..511 = 64ch x 8 chunks
        int c = i >> 3, j = i & 7;
        float4 v = ldg_cs_f4(
            x + (((size_t)(n * 64 + c)) * HH + h) * WW + w0 + j * 4);
        int wb = j * 4;
        s[(wb + 0) * 65 + c] = v.x;
        s[(wb + 1) * 65 + c] = v.y;
        s[(wb + 2) * 65 + c] = v.z;
        s[(wb + 3) * 65 + c] = v.w;
    }
    __syncthreads();

    int wcx = tid >> 3;
    int cg = (tid & 7) * 8;
    alignas(16) __half h8[8];
#pragma unroll
    for (int j = 0; j < 8; ++j)
        h8[j] = __float2half_rn(s[wcx * 65 + cg + j]);
    size_t dst = (((size_t)n * HP + (h + 1)) * HP + (w0 + wcx + 1)) * 64 + cg;
    *reinterpret_cast<uint4*>(&g_xp[dst]) = *reinterpret_cast<const uint4*>(h8);
}

// ---------------------------------------------------------------------------
// Kernel 2: finalize scales (redundant per block) + fuse ternary weights
// ---------------------------------------------------------------------------
__global__ void prep_kernel(const float* __restrict__ w,
                            const float* __restrict__ b,
                            const float* __restrict__ wc,
                            const float* __restrict__ bc,
                            const float* __restrict__ gate) {
    __shared__ float ssc[2];
    if (threadIdx.x < 2) {
        double s = 0.0;
        for (int i = 0; i < 16; ++i) s += g_part[threadIdx.x * 16 + i];
        ssc[threadIdx.x] = fmaxf((float)(s / (double)W_ELEMS), 1e-5f);
    }
    __syncthreads();
    int i = blockIdx.x * 256 + threadIdx.x;
    float g = 1.0f / (1.0f + expf(-gate[0]));
    if (i < W_ELEMS) {
        float s1 = ssc[0], s2 = ssc[1];
        float q1 = fminf(fmaxf(rintf(w[i]  / s1), -1.0f), 1.0f) * s1;
        float q2 = fminf(fmaxf(rintf(wc[i] / s2), -1.0f), 1.0f) * s2;
        int o = i / (C_IN * 9);
        int r = i - o * (C_IN * 9);
        int c = r / 9;
        int k = r - c * 9;
        g_wB[k * 4096 + o * 64 + c] = __float2half_rn(q1 + g * q2);
    }
    if (i < C_OUT)
        g_beff[i] = b[i] + g * bc[i];
}

// ---------------------------------------------------------------------------
// Kernel 3: persistent implicit-GEMM conv via HMMA.
//   R11-PROVEN mainloop (256 thr, m32n64 warps, full dy/dx/kc unroll, direct
//   epilogue).  NEW: consecutive-tile chunks per CTA + 8-slot row ring so
//   steady-state tiles stage only the 2 NEW rows (vertical reuse) and run
//   ONE wait+sync per tile.
// SMEM: B [0,73728) | A ring 8 x 16640 [73728, 206848)
// ---------------------------------------------------------------------------
#define AROW_B   16640              // 130*128
#define A_OFF    73728
#define SMEM_CONV 206848
#define NTILES2  1024               // 16 images * 64 row-pairs
#define NCTA     148

// Stage cnt padded rows starting at padded row pr0 into ring slots
// (slotbase+r)&7.  Source rows are contiguous (row stride = AROW_B bytes).
__device__ __forceinline__ void stage_rows(int cnt, int n, int pr0,
                                           int slotbase, uint32_t base, int tid) {
    const char* src = reinterpret_cast<const char*>(
        g_xp + ((size_t)n * HP + pr0) * HP * 64);
    for (int i = tid; i < cnt * 1040; i += 256) {
        int r = i / 1040;
        int k = i - r * 1040;
        int p = k >> 3, j = k & 7;
        cp16(base + A_OFF + ((slotbase + r) & 7) * AROW_B
                 + p * 128 + ((j ^ (p & 7)) << 4),
             src + (size_t)r * AROW_B + (size_t)k * 16);
    }
}

__global__ __launch_bounds__(256, 1)
void conv_kernel(float* __restrict__ out) {
    extern __shared__ char sm[];
    const uint32_t base = smem_to_u32(sm);
    const int tid  = threadIdx.x;
    const int wid  = tid >> 5;
    const int lane = tid & 31;

    // Stage all 9 weight tiles (swizzle: chunk j of oc-row nr -> j^(nr&7))
    for (int k = tid; k < 4608; k += 256) {
        int q = k & 511;
        int nr = q >> 3, j = q & 7;
        cp16(base + (k >> 9) * 8192 + nr * 128 + ((j ^ (nr & 7)) << 4),
             reinterpret_cast<const char*>(g_wB) + (size_t)k * 16);
    }
    cp_commit();

    // Contiguous tile chunk for this CTA
    const int lo = (int)(((long long)blockIdx.x * NTILES2) / NCTA);
    const int hi = (int)(((long long)(blockIdx.x + 1) * NTILES2) / NCTA);

    // Prologue: 4 rows of first tile into ring slots 0..3
    stage_rows(4, lo >> 6, (lo & 63) * 2, 0, base, tid);
    cp_commit();
    cp_wait0();
    __syncthreads();

    // Warp layout: rw = output row within pair, m0 = 32-pixel quadrant
    const int rw = wid >> 2;
    const int m0 = (wid & 3) * 32;
    const int a_pl = lane & 15, a_hk = lane >> 4;
    const int b_nl = (lane & 7) + ((lane >> 4) << 3);
    const int b_hk = (lane >> 3) & 1;

    // Per-thread bias registers: oc = nj*8 + (lane&3)*2 + {0,1}
    float bv[8][2];
#pragma unroll
    for (int nj = 0; nj < 8; ++nj) {
        bv[nj][0] = g_beff[nj * 8 + (lane & 3) * 2];
        bv[nj][1] = g_beff[nj * 8 + (lane & 3) * 2 + 1];
    }

    int ringpos = 0;
    for (int t = lo; t < hi; ++t) {
        const bool has_next = (t + 1 < hi);
        int next_ring = ringpos;
        if (has_next) {
            int nn  = (t + 1) >> 6;
            int y0n = ((t + 1) & 63) * 2;
            if (nn == (t >> 6)) {           // adjacent pair: 2 new rows
                stage_rows(2, nn, y0n + 2, ringpos + 4, base, tid);
                next_ring = (ringpos + 2) & 7;
            } else {                        // image boundary: 4 fresh rows
                stage_rows(4, nn, y0n, ringpos + 4, base, tid);
                next_ring = (ringpos + 4) & 7;
            }
            cp_commit();
        }

        float acc[2][8][4];
#pragma unroll
        for (int mi = 0; mi < 2; ++mi)
#pragma unroll
            for (int nj = 0; nj < 8; ++nj)
#pragma unroll
                for (int r = 0; r < 4; ++r) acc[mi][nj][r] = 0.0f;

#pragma unroll
        for (int dy = 0; dy < 3; ++dy) {
            const uint32_t arow = base + A_OFF +
                ((ringpos + rw + dy) & 7) * AROW_B;
#pragma unroll
            for (int dx = 0; dx < 3; ++dx) {
                const uint32_t btap = base + (dy * 3 + dx) * 8192;
#pragma unroll
                for (int kc = 0; kc < 4; ++kc) {
                    uint32_t a[2][4];
#pragma unroll
                    for (int mi = 0; mi < 2; ++mi) {
                        int pix = m0 + mi * 16 + a_pl + dx;
                        ldsm_x4(a[mi], arow + pix * 128 +
                                (((2 * kc + a_hk) ^ (pix & 7)) << 4));
                    }
#pragma unroll
                    for (int nj = 0; nj < 4; ++nj) {
                        uint32_t b[4];
                        int nn = nj * 16 + b_nl;
                        ldsm_x4(b, btap + nn * 128 +
                                (((2 * kc + b_hk) ^ (b_nl & 7)) << 4));
#pragma unroll
                        for (int mi = 0; mi < 2; ++mi) {
                            mma16816(acc[mi][nj * 2 + 0], a[mi], b + 0);
                            mma16816(acc[mi][nj * 2 + 1], a[mi], b + 2);
                        }
                    }
                }
            }
        }

        // Direct epilogue: STG.32 from fragments, bias fused in registers
        {
            const int n = t >> 6, y = (t & 63) * 2 + rw;
            float* ob = out + (size_t)n * (64 * 16384) + (size_t)y * 128;
            const int pl = lane >> 2;
#pragma unroll
            for (int mi = 0; mi < 2; ++mi) {
                int pbase = m0 + mi * 16 + pl;
#pragma unroll
                for (int nj = 0; nj < 8; ++nj) {
                    float* p0 = ob + (size_t)(nj * 8 + (lane & 3) * 2) * 16384;
                    p0[pbase]             = acc[mi][nj][0] + bv[nj][0];
                    p0[16384 + pbase]     = acc[mi][nj][1] + bv[nj][1];
                    p0[pbase + 8]         = acc[mi][nj][2] + bv[nj][0];
                    p0[16384 + pbase + 8] = acc[mi][nj][3] + bv[nj][1];
                }
            }
        }

        if (has_next) {
            cp_wait0();          // next tile's rows landed
            __syncthreads();     // visible to all warps; old readers done
            ringpos = next_ring;
        }
    }
}

// ---------------------------------------------------------------------------
extern "C" void kernel_launch(void* const* d_in, const int* in_sizes, int n_in,
                              void* d_out, int out_size) {
    const float* x  = (const float*)d_in[0];
    const float* w  = (const float*)d_in[1];
    const float* b  = (const float*)d_in[2];
    const float* wc = (const float*)d_in[3];
    const float* bc = (const float*)d_in[4];
    const float* gt = (const float*)d_in[5];
    float* out = (float*)d_out;

    static bool attr_set = false;
    if (!attr_set) {
        cudaFuncSetAttribute(conv_kernel,
                             cudaFuncAttributeMaxDynamicSharedMemorySize, SMEM_CONV);
        attr_set = true;
    }

    transpose_scale_kernel<<<8192 + 32, 256>>>(x, w, wc);
    prep_kernel<<<(W_ELEMS + 255) / 256, 256>>>(w, b, wc, bc, gt);
    conv_kernel<<<NCTA, 256, SMEM_CONV>>>(out);
}